// round 11
// baseline (speedup 1.0000x reference)
#include <cuda_runtime.h>

#define N_ZQ   2097152   // 8*64*64*64
#define N_IDX  32768
#define K_ROWS 8192
#define D_DIM  64
#define NB1    512
#define NT     256

// Device scratch (no allocation). g_tick1 is MONOTONE: 2^32 % 512 == 0, so
// last-arrival detection wraps cleanly across graph replays. All scratch is
// fully rewritten every launch -> deterministic.
__device__ unsigned long long g_amin[NB1];
__device__ float g_S[NB1 * D_DIM];    // per-block column sums
__device__ float g_qpart[NB1];        // per-block sum of squares
__device__ unsigned int g_tick1;
__device__ int g_kmin;
__device__ float g_bookrow[D_DIM];

// ---------------------------------------------------------------------------
// Kernel 1: read-everything + reduce-everything. 512x256.
// Per thread: 1 book float4 + 4 input float4s, all front-batched (MLP=5).
//  - book: 16 consecutive lanes share a row -> shfl butterfly -> block argmin
//  - input: per-thread w-slot is chunk-invariant (stride 131072 ≡ 0 mod 16),
//    so thread owns 4 column sums (w0..w0+3) + a squares accumulator.
// Every thread that writes global scratch fences BEFORE the arrival ticket
// (the fence must belong to the storing thread). Last-arriving block reduces
// argmin, column sums and Q, and writes g_kmin, g_bookrow and the LOSS.
// ---------------------------------------------------------------------------
__global__ void __launch_bounds__(NT, 4)
k_reduce(const float* __restrict__ in, const float* __restrict__ book,
         float* __restrict__ out, int out_size) {
    __shared__ unsigned long long s[NT];
    __shared__ float sS[8][D_DIM];
    __shared__ float sq[8];
    __shared__ float sbk[D_DIM];
    __shared__ double sdA[D_DIM];   // cross-term partials
    __shared__ double sdB[D_DIM];   // b^2 partials
    __shared__ double sdq[8];
    __shared__ int last;

    int t = threadIdx.x, b = blockIdx.x;
    int gtid = b * NT + t;
    const int stride = NB1 * NT;                // 131072

    const float4* in4 = reinterpret_cast<const float4*>(in);
    const float4* bk4 = reinterpret_cast<const float4*>(book);

    // ---- front-batched independent loads (5 in flight) ----
    float4 bk = bk4[gtid];
    float4 x0 = in4[gtid];
    float4 x1 = in4[gtid + stride];
    float4 x2 = in4[gtid + 2 * stride];
    float4 x3 = in4[gtid + 3 * stride];

    // ---- book argmin partial ----
    float bn = bk.x * bk.x;
    bn = fmaf(bk.y, bk.y, bn);
    bn = fmaf(bk.z, bk.z, bn);
    bn = fmaf(bk.w, bk.w, bn);
#pragma unroll
    for (int off = 1; off < 16; off <<= 1)
        bn += __shfl_xor_sync(0xffffffffu, bn, off);
    unsigned long long key =
        ((unsigned long long)__float_as_uint(bn) << 32) | (unsigned)(gtid >> 4);
    s[t] = key;

    // ---- input stats ----
    float s0 = (x0.x + x1.x) + (x2.x + x3.x);
    float s1 = (x0.y + x1.y) + (x2.y + x3.y);
    float s2 = (x0.z + x1.z) + (x2.z + x3.z);
    float s3 = (x0.w + x1.w) + (x2.w + x3.w);
    float q = x0.x * x0.x;
    q = fmaf(x0.y, x0.y, q); q = fmaf(x0.z, x0.z, q); q = fmaf(x0.w, x0.w, q);
    q = fmaf(x1.x, x1.x, q); q = fmaf(x1.y, x1.y, q);
    q = fmaf(x1.z, x1.z, q); q = fmaf(x1.w, x1.w, q);
    q = fmaf(x2.x, x2.x, q); q = fmaf(x2.y, x2.y, q);
    q = fmaf(x2.z, x2.z, q); q = fmaf(x2.w, x2.w, q);
    q = fmaf(x3.x, x3.x, q); q = fmaf(x3.y, x3.y, q);
    q = fmaf(x3.z, x3.z, q); q = fmaf(x3.w, x3.w, q);

    // q: full-warp reduce
    float qv = q;
#pragma unroll
    for (int off = 16; off > 0; off >>= 1)
        qv += __shfl_down_sync(0xffffffffu, qv, off);
    if ((t & 31) == 0) sq[t >> 5] = qv;

    // S: lanes l and l+16 share w0 = (l&15)*4
    s0 += __shfl_down_sync(0xffffffffu, s0, 16);
    s1 += __shfl_down_sync(0xffffffffu, s1, 16);
    s2 += __shfl_down_sync(0xffffffffu, s2, 16);
    s3 += __shfl_down_sync(0xffffffffu, s3, 16);
    if ((t & 31) < 16) {
        int w0 = (t & 15) * 4;
        int w = t >> 5;
        sS[w][w0]     = s0;
        sS[w][w0 + 1] = s1;
        sS[w][w0 + 2] = s2;
        sS[w][w0 + 3] = s3;
    }
    __syncthreads();

    // block argmin tree
#pragma unroll
    for (int off = NT / 2; off > 0; off >>= 1) {
        if (t < off) {
            unsigned long long o = s[t + off];
            if (o < s[t]) s[t] = o;
        }
        __syncthreads();
    }

    // publish block partials; WRITING THREADS fence before the ticket
    if (t < D_DIM) {
        float acc = sS[0][t];
#pragma unroll
        for (int j = 1; j < 8; ++j) acc += sS[j][t];
        g_S[b * D_DIM + t] = acc;
        __threadfence();
    }
    if (t == 0) {
        g_amin[b] = s[0];
        float qb = sq[0];
#pragma unroll
        for (int j = 1; j < 8; ++j) qb += sq[j];
        g_qpart[b] = qb;
        __threadfence();
        unsigned r = atomicAdd(&g_tick1, 1u);
        last = ((r & (NB1 - 1)) == NB1 - 1);
    }
    __syncthreads();
    if (!last) return;

    // ================= last-arriving block: final reductions =============
    if (t == 0) __threadfence();   // acquire side
    __syncthreads();

    // global argmin
    {
        volatile unsigned long long* ga = g_amin;
        unsigned long long a = ga[t], c = ga[t + NT];
        s[t] = (c < a) ? c : a;
    }
    __syncthreads();
#pragma unroll
    for (int off = NT / 2; off > 0; off >>= 1) {
        if (t < off) {
            unsigned long long o = s[t + off];
            if (o < s[t]) s[t] = o;
        }
        __syncthreads();
    }
    int kmin = (int)(s[0] & 0xffffffffu);
    if (t < D_DIM) {
        float bw = book[(size_t)kmin * D_DIM + t];
        sbk[t] = bw;
        g_bookrow[t] = bw;       // visible to K2 via launch boundary
    }
    if (t == 0) g_kmin = kmin;

    // column-sum reduction: thread t -> column t&63, chunk t>>6 (128 blocks)
    {
        int w = t & 63, chunk = t >> 6;
        const float* gs = g_S + (size_t)(chunk * 128) * D_DIM + w;
        float acc = 0.0f;
#pragma unroll 8
        for (int i = 0; i < 128; ++i) acc += gs[(size_t)i * D_DIM];
        sS[chunk][w] = acc;      // rows 0..3 used
    }
    // Q reduction
    {
        double dq = (double)g_qpart[t] + (double)g_qpart[t + NT];
#pragma unroll
        for (int off = 16; off > 0; off >>= 1)
            dq += __shfl_down_sync(0xffffffffu, dq, off);
        if ((t & 31) == 0) sdq[t >> 5] = dq;
    }
    __syncthreads();

    if (t < D_DIM) {
        double Sw = (double)sS[0][t] + (double)sS[1][t]
                  + (double)sS[2][t] + (double)sS[3][t];
        double bw = (double)sbk[t];
        sdA[t] = bw * Sw;
        sdB[t] = bw * bw;
    }
    __syncthreads();
#pragma unroll
    for (int off = 32; off > 0; off >>= 1) {
        if (t < off) { sdA[t] += sdA[t + off]; sdB[t] += sdB[t + off]; }
        __syncthreads();
    }
    if (t == 0 && out_size >= N_ZQ + N_IDX + 1) {
        double Q = 0.0;
#pragma unroll
        for (int j = 0; j < 8; ++j) Q += sdq[j];
        double loss_sum = Q - 2.0 * sdA[0] + (double)N_IDX * sdB[0];
        out[N_ZQ + N_IDX] = (float)(1.25 * loss_sum / (double)N_ZQ);
    }
}

// ---------------------------------------------------------------------------
// Kernel 2: pure store stream — NO DRAM reads, so no latency exposure.
// 512x256, 4 broadcast float4 stores/thread (exact fit) + idx fill.
// z_q value slot (j>>10)&63 is chunk-invariant (stride ≡ 0 mod 1024).
// ---------------------------------------------------------------------------
__global__ void __launch_bounds__(NT, 4)
k_store(float* __restrict__ out, int out_size) {
    int t = threadIdx.x, b = blockIdx.x;
    int gtid = b * NT + t;
    const int stride = NB1 * NT;               // 131072

    float vz = g_bookrow[(gtid >> 10) & 63];
    float4 vq = make_float4(vz, vz, vz, vz);
    float4* out4 = reinterpret_cast<float4*>(out);

    out4[gtid]              = vq;
    out4[gtid + stride]     = vq;
    out4[gtid + 2 * stride] = vq;
    out4[gtid + 3 * stride] = vq;

    if (out_size >= N_ZQ + N_IDX && gtid < N_IDX / 4) {
        float fk = (float)g_kmin;
        out4[N_ZQ / 4 + gtid] = make_float4(fk, fk, fk, fk);
    }
}

extern "C" void kernel_launch(void* const* d_in, const int* in_sizes, int n_in,
                              void* d_out, int out_size) {
    const float* input = (const float*)d_in[0];
    const float* book  = (const float*)d_in[1];
    if (n_in >= 2 && in_sizes[0] == K_ROWS * D_DIM && in_sizes[1] == N_ZQ) {
        const float* tmp = input; input = book; book = tmp;
    }
    k_reduce<<<NB1, NT>>>(input, book, (float*)d_out, out_size);
    k_store<<<NB1, NT>>>((float*)d_out, out_size);
}

// round 14
// speedup vs baseline: 1.1212x; 1.1212x over previous
#include <cuda_runtime.h>
#include <cstdint>

#define N_ZQ   2097152   // 8*64*64*64
#define N_IDX  32768
#define K_ROWS 8192
#define D_DIM  64
#define NB     512
#define NT     256

// Device scratch. All counters MONOTONE (2^32 % 512 == 0): generation
// arithmetic wraps cleanly across graph replays; no resets; deterministic.
__device__ unsigned long long g_amin[NB];
__device__ float g_S[D_DIM * NB];        // transposed: g_S[w*NB + b]
__device__ float g_qpart[NB];
__device__ unsigned int g_tick;
__device__ unsigned int g_release;       // separate line from g_tick
__device__ int g_kmin;
__device__ float g_bookrow[D_DIM];

__device__ __forceinline__ unsigned ld_cv_u32(const unsigned* p) {
    unsigned v;
    asm volatile("ld.global.cv.u32 %0, [%1];" : "=r"(v) : "l"(p));
    return v;
}

__global__ void __launch_bounds__(NT, 4)
k_fused(const float* __restrict__ in, const float* __restrict__ book,
        float* __restrict__ out, int out_size) {
    __shared__ unsigned long long s[NT];
    __shared__ float sS[8][D_DIM];
    __shared__ float sq[8];
    __shared__ float sSw[D_DIM];
    __shared__ double sdA[D_DIM];
    __shared__ double sdB[D_DIM];
    __shared__ double sdq[8];
    __shared__ int s_last;
    __shared__ unsigned s_gen;

    int t = threadIdx.x, b = blockIdx.x;
    int gtid = b * NT + t;
    const int stride = NB * NT;                 // 131072

    const float4* in4 = reinterpret_cast<const float4*>(in);
    const float4* bk4 = reinterpret_cast<const float4*>(book);

    // ---------------- Phase 1: all reads, front-batched (MLP=5) ----------
    float4 bk = bk4[gtid];
    float4 x0 = in4[gtid];
    float4 x1 = in4[gtid + stride];
    float4 x2 = in4[gtid + 2 * stride];
    float4 x3 = in4[gtid + 3 * stride];

    // book argmin partial: 16 lanes/row, shfl butterfly; positive-float bits
    // are monotone so u64-min of (norm<<32)|row is argmin w/ low-index ties.
    float bn = bk.x * bk.x;
    bn = fmaf(bk.y, bk.y, bn);
    bn = fmaf(bk.z, bk.z, bn);
    bn = fmaf(bk.w, bk.w, bn);
#pragma unroll
    for (int off = 1; off < 16; off <<= 1)
        bn += __shfl_xor_sync(0xffffffffu, bn, off);
    s[t] = ((unsigned long long)__float_as_uint(bn) << 32) | (unsigned)(gtid >> 4);

    // input stats for closed-form loss (proven R11):
    //   loss_sum = Q - 2*sum_w b_w*S_w + 32768*sum_w b_w^2
    float s0 = (x0.x + x1.x) + (x2.x + x3.x);
    float s1 = (x0.y + x1.y) + (x2.y + x3.y);
    float s2 = (x0.z + x1.z) + (x2.z + x3.z);
    float s3 = (x0.w + x1.w) + (x2.w + x3.w);
    float q = x0.x * x0.x;
    q = fmaf(x0.y, x0.y, q); q = fmaf(x0.z, x0.z, q); q = fmaf(x0.w, x0.w, q);
    q = fmaf(x1.x, x1.x, q); q = fmaf(x1.y, x1.y, q);
    q = fmaf(x1.z, x1.z, q); q = fmaf(x1.w, x1.w, q);
    q = fmaf(x2.x, x2.x, q); q = fmaf(x2.y, x2.y, q);
    q = fmaf(x2.z, x2.z, q); q = fmaf(x2.w, x2.w, q);
    q = fmaf(x3.x, x3.x, q); q = fmaf(x3.y, x3.y, q);
    q = fmaf(x3.z, x3.z, q); q = fmaf(x3.w, x3.w, q);

#pragma unroll
    for (int off = 16; off > 0; off >>= 1)
        q += __shfl_down_sync(0xffffffffu, q, off);
    if ((t & 31) == 0) sq[t >> 5] = q;

    // column sums: lanes l, l+16 share w0 = (l&15)*4 (w-slot chunk-invariant)
    s0 += __shfl_down_sync(0xffffffffu, s0, 16);
    s1 += __shfl_down_sync(0xffffffffu, s1, 16);
    s2 += __shfl_down_sync(0xffffffffu, s2, 16);
    s3 += __shfl_down_sync(0xffffffffu, s3, 16);
    if ((t & 31) < 16) {
        int w0 = (t & 15) * 4, w = t >> 5;
        sS[w][w0] = s0; sS[w][w0 + 1] = s1; sS[w][w0 + 2] = s2; sS[w][w0 + 3] = s3;
    }
    __syncthreads();

#pragma unroll
    for (int off = NT / 2; off > 0; off >>= 1) {
        if (t < off) {
            unsigned long long o = s[t + off];
            if (o < s[t]) s[t] = o;
        }
        __syncthreads();
    }

    // publish block partials
    if (t < D_DIM) {
        float acc = sS[0][t];
#pragma unroll
        for (int j = 1; j < 8; ++j) acc += sS[j][t];
        g_S[t * NB + b] = acc;                  // transposed
    }
    if (t == 0) {
        g_amin[b] = s[0];
        float qb = sq[0];
#pragma unroll
        for (int j = 1; j < 8; ++j) qb += sq[j];
        g_qpart[b] = qb;
    }
    __syncthreads();   // ALL block writes complete before t0's fence+ticket
    if (t == 0) {
        __threadfence();
        unsigned r = atomicAdd(&g_tick, 1u);
        s_last = ((r & (NB - 1)) == NB - 1);
        s_gen  = (r >> 9) + 1;                  // this generation's release value
    }
    __syncthreads();

    // ---------------- Barrier resolution ---------------------------------
    if (s_last) {
        if (t == 0) __threadfence();            // acquire side
        __syncthreads();
        // global argmin
        {
            volatile unsigned long long* ga = g_amin;
            unsigned long long a = ga[t], c = ga[t + NT];
            s[t] = (c < a) ? c : a;
        }
        __syncthreads();
#pragma unroll
        for (int off = NT / 2; off > 0; off >>= 1) {
            if (t < off) {
                unsigned long long o = s[t + off];
                if (o < s[t]) s[t] = o;
            }
            __syncthreads();
        }
        int km = (int)(s[0] & 0xffffffffu);
        float bw = 0.0f;
        if (t < D_DIM) {
            bw = book[(size_t)km * D_DIM + t];
            g_bookrow[t] = bw;
        }
        if (t == 0) g_kmin = km;
        __syncthreads();   // <-- the fix vs R7: bookrow stores BEFORE release
        if (t == 0) {
            __threadfence();
            asm volatile("st.global.cg.u32 [%0], %1;"
                         :: "l"(&g_release), "r"(s_gen) : "memory");
        }

        // loss (overlaps the other 511 blocks' stores)
        {
            int w = t >> 2, c = t & 3;
            const float4* gs4 =
                reinterpret_cast<const float4*>(g_S + w * NB) + c * 32;
            float a0 = 0.f, a1 = 0.f, a2 = 0.f, a3 = 0.f;
#pragma unroll
            for (int i = 0; i < 32; i += 4) {
                float4 v0 = gs4[i], v1 = gs4[i+1], v2 = gs4[i+2], v3 = gs4[i+3];
                a0 += (v0.x + v0.y) + (v0.z + v0.w);
                a1 += (v1.x + v1.y) + (v1.z + v1.w);
                a2 += (v2.x + v2.y) + (v2.z + v2.w);
                a3 += (v3.x + v3.y) + (v3.z + v3.w);
            }
            float sw = (a0 + a1) + (a2 + a3);
            sw += __shfl_xor_sync(0xffffffffu, sw, 1);
            sw += __shfl_xor_sync(0xffffffffu, sw, 2);
            if (c == 0) sSw[w] = sw;
        }
        {
            double dq = (double)g_qpart[t] + (double)g_qpart[t + NT];
#pragma unroll
            for (int off = 16; off > 0; off >>= 1)
                dq += __shfl_down_sync(0xffffffffu, dq, off);
            if ((t & 31) == 0) sdq[t >> 5] = dq;
        }
        __syncthreads();
        if (t < D_DIM) {
            double dbw = (double)bw;
            sdA[t] = dbw * (double)sSw[t];
            sdB[t] = dbw * dbw;
        }
        __syncthreads();
#pragma unroll
        for (int off = 32; off > 0; off >>= 1) {
            if (t < off) { sdA[t] += sdA[t + off]; sdB[t] += sdB[t + off]; }
            __syncthreads();
        }
        if (t == 0 && out_size >= N_ZQ + N_IDX + 1) {
            double Q = 0.0;
#pragma unroll
            for (int j = 0; j < 8; ++j) Q += sdq[j];
            double loss_sum = Q - 2.0 * sdA[0] + (double)N_IDX * sdB[0];
            out[N_ZQ + N_IDX] = (float)(1.25 * loss_sum / (double)N_ZQ);
        }
    } else {
        if (t == 0) {
            unsigned tgt = s_gen;
            while ((int)(ld_cv_u32(&g_release) - tgt) < 0) __nanosleep(64);
            __threadfence();                    // acquire for g_bookrow/g_kmin
        }
        __syncthreads();
    }

    // ---------------- Phase 2: broadcast stores --------------------------
    // z_q value slot (4j>>12)&63 = (j>>10)&63 is chunk-invariant
    // (stride % 1024 == 0); idx is the constant argmin index.
    float vz = g_bookrow[(gtid >> 10) & 63];
    float4 vq = make_float4(vz, vz, vz, vz);
    float4* out4 = reinterpret_cast<float4*>(out);
    out4[gtid]              = vq;
    out4[gtid + stride]     = vq;
    out4[gtid + 2 * stride] = vq;
    out4[gtid + 3 * stride] = vq;

    if (out_size >= N_ZQ + N_IDX && gtid < N_IDX / 4) {
        float fk = (float)g_kmin;
        out4[N_ZQ / 4 + gtid] = make_float4(fk, fk, fk, fk);
    }
}

extern "C" void kernel_launch(void* const* d_in, const int* in_sizes, int n_in,
                              void* d_out, int out_size) {
    const float* input = (const float*)d_in[0];
    const float* book  = (const float*)d_in[1];
    if (n_in >= 2 && in_sizes[0] == K_ROWS * D_DIM && in_sizes[1] == N_ZQ) {
        const float* tmp = input; input = book; book = tmp;
    }
    k_fused<<<NB, NT>>>(input, book, (float*)d_out, out_size);
}

// round 16
// speedup vs baseline: 1.2759x; 1.1379x over previous
#include <cuda_runtime.h>

#define N_ZQ   2097152   // 8*64*64*64
#define N_IDX  32768
#define K_ROWS 8192
#define D_DIM  64
#define NB1    512       // argmin blocks (2^9)
#define NB2    592       // main blocks (4 per SM * 148)
#define NT     256
#define N_F4   (N_ZQ / 4)

// Device scratch (no allocation). g_tick1 is monotone (2^32 % 512 == 0);
// g_tick2 uses an explicit mod-NB2 generation compare. Both wrap safely
// across unlimited graph replays; all scratch rewritten每 launch.
__device__ unsigned long long g_amin[NB1];
__device__ double g_losspart[NB2];
__device__ unsigned int g_tick1;
__device__ unsigned long long g_tick2;   // 64-bit: % NB2 never wraps in practice
__device__ int g_kmin;
__device__ float g_bookrow[D_DIM];

// ---------------------------------------------------------------------------
// Kernel 1: book argmin — fastest measured form (R10): 512x256, ONE float4
// per thread (8192 rows x 16 float4s), 16 lanes/row shfl butterfly, one DRAM
// round trip. Last-arriving block reduces 512 partials, publishes g_kmin and
// the winning 64-float row. Launch boundary = consumer sync.
// ---------------------------------------------------------------------------
__global__ void __launch_bounds__(NT, 4)
k_argmin(const float* __restrict__ book) {
    __shared__ unsigned long long s[NT];
    __shared__ int last;
    int t = threadIdx.x, b = blockIdx.x;

    int f = b * NT + t;
    float4 v = reinterpret_cast<const float4*>(book)[f];
    float acc = v.x * v.x;
    acc = fmaf(v.y, v.y, acc);
    acc = fmaf(v.z, v.z, acc);
    acc = fmaf(v.w, v.w, acc);
#pragma unroll
    for (int off = 1; off < 16; off <<= 1)
        acc += __shfl_xor_sync(0xffffffffu, acc, off);
    // positive-float bits are monotone: u64-min = (min norm, lowest row)
    unsigned long long key =
        ((unsigned long long)__float_as_uint(acc) << 32) | (unsigned)(f >> 4);
    s[t] = key;
    __syncthreads();
#pragma unroll
    for (int off = NT / 2; off > 0; off >>= 1) {
        if (t < off) {
            unsigned long long o = s[t + off];
            if (o < s[t]) s[t] = o;
        }
        __syncthreads();
    }
    if (t == 0) {
        g_amin[b] = s[0];
        __threadfence();
        unsigned r = atomicAdd(&g_tick1, 1u);
        last = ((r & (NB1 - 1)) == NB1 - 1);
    }
    __syncthreads();
    if (last) {
        volatile unsigned long long* ga = g_amin;
        unsigned long long a = ga[t], c = ga[t + NT];
        s[t] = (c < a) ? c : a;
        __syncthreads();
#pragma unroll
        for (int off = NT / 2; off > 0; off >>= 1) {
            if (t < off) {
                unsigned long long o = s[t + off];
                if (o < s[t]) s[t] = o;
            }
            __syncthreads();
        }
        int kmin = (int)(s[0] & 0xffffffffu);
        if (t < D_DIM) g_bookrow[t] = book[(size_t)kmin * D_DIM + t];
        if (t == 0) g_kmin = kmin;
    }
}

// ---------------------------------------------------------------------------
// Kernel 2: R3's proven streaming shape — 592 blocks x 256, grid-stride with
// 4 float4 iterations — plus: bookrow from L2 (no argmin re-reduce) and the
// loss finalized by the last-arriving block (no third launch).
// ---------------------------------------------------------------------------
__global__ void __launch_bounds__(NT, 4)
k_main(const float* __restrict__ in, float* __restrict__ out, int out_size) {
    __shared__ float sbk[D_DIM];
    __shared__ float swr[8];
    __shared__ int last;
    int t = threadIdx.x, b = blockIdx.x;

    if (t < D_DIM) sbk[t] = g_bookrow[t];
    int kmin = g_kmin;
    __syncthreads();

    int gtid = b * NT + t;
    const int gstride = NB2 * NT;               // 151552

    const float4* in4  = reinterpret_cast<const float4*>(in);
    float4*       out4 = reinterpret_cast<float4*>(out);

    float lsum = 0.0f;
#pragma unroll 4
    for (int j = gtid; j < N_F4; j += gstride) {
        float4 x = in4[j];
        int w0 = (j << 2) & 63;
        float d0 = sbk[w0]     - x.x;
        float d1 = sbk[w0 + 1] - x.y;
        float d2 = sbk[w0 + 2] - x.z;
        float d3 = sbk[w0 + 3] - x.w;
        lsum = fmaf(d0, d0, lsum);
        lsum = fmaf(d1, d1, lsum);
        lsum = fmaf(d2, d2, lsum);
        lsum = fmaf(d3, d3, lsum);
        float v = sbk[(j >> 10) & 63];          // z_q flat value slot
        out4[j] = make_float4(v, v, v, v);
    }

    // idx section: constant argmin index as float
    if (out_size >= N_ZQ + N_IDX && gtid < N_IDX / 4) {
        float fk = (float)kmin;
        out4[N_ZQ / 4 + gtid] = make_float4(fk, fk, fk, fk);
    }

    // block loss partial; last-arriving block finalizes
#pragma unroll
    for (int off = 16; off > 0; off >>= 1)
        lsum += __shfl_down_sync(0xffffffffu, lsum, off);
    if ((t & 31) == 0) swr[t >> 5] = lsum;
    __syncthreads();
    if (t == 0) {
        double ds = 0.0;
#pragma unroll
        for (int i = 0; i < 8; ++i) ds += (double)swr[i];
        g_losspart[b] = ds;
        __threadfence();
        unsigned long long r = atomicAdd(&g_tick2, 1ull);
        last = ((r % NB2) == NB2 - 1);
    }
    __syncthreads();
    if (last) {
        __shared__ double sd[NT];
        volatile double* gl = g_losspart;
        double acc = 0.0;
        for (int i = t; i < NB2; i += NT) acc += gl[i];
        sd[t] = acc;
        __syncthreads();
#pragma unroll
        for (int off = NT / 2; off > 0; off >>= 1) {
            if (t < off) sd[t] += sd[t + off];
            __syncthreads();
        }
        if (t == 0 && out_size >= N_ZQ + N_IDX + 1)
            out[N_ZQ + N_IDX] = (float)(1.25 * sd[0] / (double)N_ZQ);
    }
}

extern "C" void kernel_launch(void* const* d_in, const int* in_sizes, int n_in,
                              void* d_out, int out_size) {
    const float* input = (const float*)d_in[0];
    const float* book  = (const float*)d_in[1];
    if (n_in >= 2 && in_sizes[0] == K_ROWS * D_DIM && in_sizes[1] == N_ZQ) {
        const float* tmp = input; input = book; book = tmp;
    }
    k_argmin<<<NB1, NT>>>(book);
    k_main<<<NB2, NT>>>(input, (float*)d_out, out_size);
}

// round 17
// speedup vs baseline: 1.2786x; 1.0022x over previous
#include <cuda_runtime.h>

#define N_ZQ   2097152   // 8*64*64*64
#define N_IDX  32768
#define K_ROWS 8192
#define D_DIM  64
#define NB     512
#define NT     256

// Device scratch (no allocation). Ticket counters MONOTONE (2^32 % 512 == 0):
// wrap-safe across unlimited graph replays, no resets, deterministic.
__device__ unsigned long long g_amin[NB];
__device__ double g_losspart[NB];
__device__ unsigned int g_tick1, g_tick2;
__device__ int g_kmin;
__device__ float g_bookrow[D_DIM];

// ---------------------------------------------------------------------------
// Primary kernel: book argmin (R10-proven form). 512x256, ONE float4/thread
// covers 8192 rows x 16 float4s; 16 lanes/row shfl butterfly; one DRAM round
// trip. Last-arriving block reduces the 512 partials, publishes g_kmin and
// the winning 64-float row. PDL completion (implicit, at grid end) releases
// the secondary kernel's cudaGridDependencySynchronize().
// ---------------------------------------------------------------------------
__global__ void __launch_bounds__(NT, 4)
k_argmin(const float* __restrict__ book) {
    __shared__ unsigned long long s[NT];
    __shared__ int last;
    int t = threadIdx.x, b = blockIdx.x;

    int f = b * NT + t;
    float4 v = reinterpret_cast<const float4*>(book)[f];
    float acc = v.x * v.x;
    acc = fmaf(v.y, v.y, acc);
    acc = fmaf(v.z, v.z, acc);
    acc = fmaf(v.w, v.w, acc);
#pragma unroll
    for (int off = 1; off < 16; off <<= 1)
        acc += __shfl_xor_sync(0xffffffffu, acc, off);
    // positive-float bits monotone: u64-min = (min norm, lowest row)
    unsigned long long key =
        ((unsigned long long)__float_as_uint(acc) << 32) | (unsigned)(f >> 4);
    s[t] = key;
    __syncthreads();
#pragma unroll
    for (int off = NT / 2; off > 0; off >>= 1) {
        if (t < off) {
            unsigned long long o = s[t + off];
            if (o < s[t]) s[t] = o;
        }
        __syncthreads();
    }
    if (t == 0) {
        g_amin[b] = s[0];
        __threadfence();
        unsigned r = atomicAdd(&g_tick1, 1u);
        last = ((r & (NB - 1)) == NB - 1);
    }
    __syncthreads();
    if (last) {
        volatile unsigned long long* ga = g_amin;
        unsigned long long a = ga[t], c = ga[t + NT];
        s[t] = (c < a) ? c : a;
        __syncthreads();
#pragma unroll
        for (int off = NT / 2; off > 0; off >>= 1) {
            if (t < off) {
                unsigned long long o = s[t + off];
                if (o < s[t]) s[t] = o;
            }
            __syncthreads();
        }
        int kmin = (int)(s[0] & 0xffffffffu);
        if (t < D_DIM) g_bookrow[t] = book[(size_t)kmin * D_DIM + t];
        if (t == 0) g_kmin = kmin;
        __threadfence();   // ensure visibility before grid-completion trigger
    }
}

// ---------------------------------------------------------------------------
// Secondary kernel (PDL): launched with programmatic stream serialization so
// it starts WHILE k_argmin runs. Pre-sync phase: input loads + kmin-
// independent loss stats (closed form proven R11):
//   lsum = q - 2*sum_i b_i*s_i + 4*sum_i b_i^2   per thread (w-invariant).
// Then cudaGridDependencySynchronize() -> bookrow-dependent stores + loss.
// Exact fit: 512*256*4 float4s, stride 131072 (mult of 16 and 1024 -> both
// derived indices chunk-invariant).
// ---------------------------------------------------------------------------
__global__ void __launch_bounds__(NT, 4)
k_main(const float* __restrict__ in, float* __restrict__ out, int out_size) {
    __shared__ float swr[8];
    __shared__ int last;
    int t = threadIdx.x, b = blockIdx.x;
    int gtid = b * NT + t;
    const int stride = NB * NT;                 // 131072

    const float4* in4  = reinterpret_cast<const float4*>(in);
    float4*       out4 = reinterpret_cast<float4*>(out);

    // ---- pre-sync: front-batched loads + kmin-independent stats ----
    float4 x0 = in4[gtid];
    float4 x1 = in4[gtid + stride];
    float4 x2 = in4[gtid + 2 * stride];
    float4 x3 = in4[gtid + 3 * stride];

    float s0 = (x0.x + x1.x) + (x2.x + x3.x);
    float s1 = (x0.y + x1.y) + (x2.y + x3.y);
    float s2 = (x0.z + x1.z) + (x2.z + x3.z);
    float s3 = (x0.w + x1.w) + (x2.w + x3.w);
    float q = x0.x * x0.x;
    q = fmaf(x0.y, x0.y, q); q = fmaf(x0.z, x0.z, q); q = fmaf(x0.w, x0.w, q);
    q = fmaf(x1.x, x1.x, q); q = fmaf(x1.y, x1.y, q);
    q = fmaf(x1.z, x1.z, q); q = fmaf(x1.w, x1.w, q);
    q = fmaf(x2.x, x2.x, q); q = fmaf(x2.y, x2.y, q);
    q = fmaf(x2.z, x2.z, q); q = fmaf(x2.w, x2.w, q);
    q = fmaf(x3.x, x3.x, q); q = fmaf(x3.y, x3.y, q);
    q = fmaf(x3.z, x3.z, q); q = fmaf(x3.w, x3.w, q);

    // ---- wait for k_argmin grid completion (PDL) ----
    cudaGridDependencySynchronize();

    // ---- post-sync: bookrow-dependent work ----
    int kmin = g_kmin;
    int w0 = (gtid << 2) & 63;                  // chunk-invariant
    float b0 = g_bookrow[w0];
    float b1 = g_bookrow[w0 + 1];
    float b2 = g_bookrow[w0 + 2];
    float b3 = g_bookrow[w0 + 3];
    float vz = g_bookrow[(gtid >> 10) & 63];

    float dot = b0 * s0;
    dot = fmaf(b1, s1, dot);
    dot = fmaf(b2, s2, dot);
    dot = fmaf(b3, s3, dot);
    float nb = b0 * b0;
    nb = fmaf(b1, b1, nb);
    nb = fmaf(b2, b2, nb);
    nb = fmaf(b3, b3, nb);
    float lsum = fmaf(-2.0f, dot, q) + 4.0f * nb;

    float4 vq = make_float4(vz, vz, vz, vz);
    out4[gtid]              = vq;
    out4[gtid + stride]     = vq;
    out4[gtid + 2 * stride] = vq;
    out4[gtid + 3 * stride] = vq;

    if (out_size >= N_ZQ + N_IDX && gtid < N_IDX / 4) {
        float fk = (float)kmin;
        out4[N_ZQ / 4 + gtid] = make_float4(fk, fk, fk, fk);
    }

    // block loss partial; last-arriving block finalizes (R10-proven)
#pragma unroll
    for (int off = 16; off > 0; off >>= 1)
        lsum += __shfl_down_sync(0xffffffffu, lsum, off);
    if ((t & 31) == 0) swr[t >> 5] = lsum;
    __syncthreads();
    if (t == 0) {
        double ds = 0.0;
#pragma unroll
        for (int i = 0; i < 8; ++i) ds += (double)swr[i];
        g_losspart[b] = ds;
        __threadfence();
        unsigned r = atomicAdd(&g_tick2, 1u);
        last = ((r & (NB - 1)) == NB - 1);
    }
    __syncthreads();
    if (last) {
        __shared__ double sd[NT];
        volatile double* gl = g_losspart;
        sd[t] = gl[t] + gl[t + NT];
        __syncthreads();
#pragma unroll
        for (int off = NT / 2; off > 0; off >>= 1) {
            if (t < off) sd[t] += sd[t + off];
            __syncthreads();
        }
        if (t == 0 && out_size >= N_ZQ + N_IDX + 1)
            out[N_ZQ + N_IDX] = (float)(1.25 * sd[0] / (double)N_ZQ);
    }
}

extern "C" void kernel_launch(void* const* d_in, const int* in_sizes, int n_in,
                              void* d_out, int out_size) {
    const float* input = (const float*)d_in[0];
    const float* book  = (const float*)d_in[1];
    if (n_in >= 2 && in_sizes[0] == K_ROWS * D_DIM && in_sizes[1] == N_ZQ) {
        const float* tmp = input; input = book; book = tmp;
    }
    float* out = (float*)d_out;

    k_argmin<<<NB, NT>>>(book);

    // PDL launch: k_main may start while k_argmin is still running; its
    // cudaGridDependencySynchronize() gates the kmin-dependent phase.
    cudaLaunchConfig_t cfg = {};
    cfg.gridDim  = dim3(NB, 1, 1);
    cfg.blockDim = dim3(NT, 1, 1);
    cudaLaunchAttribute attrs[1];
    attrs[0].id = cudaLaunchAttributeProgrammaticStreamSerialization;
    attrs[0].val.programmaticStreamSerializationAllowed = 1;
    cfg.attrs = attrs;
    cfg.numAttrs = 1;
    cudaLaunchKernelEx(&cfg, k_main, input, out, out_size);
}